// round 15
// baseline (speedup 1.0000x reference)
#include <cuda_runtime.h>
#include <cuda_fp16.h>
#include <cstdint>

// ---------------------------------------------------------------------------
// BitNetLinear (sm_103 portable path):
//   out = (x @ qw^T) * w_scale + bias * input_scale   (input_scale cancels in
//   the GEMM; x fed raw as fp16)
// GEMM M=N=K=4096: mma.sync.m16n8k16 fp16->fp32, ldmatrix.x4,
// CTA 128x128 / warp 64x64, BK=32, 4 stages, 2 CTAs/SM (R9 mainloop, frozen).
// R15: GEMM untouched (R9 verified optimum); prep passes unrolled x4/x2 with
// front-batched loads (MLP 1->4) for DRAM-latency overlap. Same add order ->
// bitwise-identical scales and output.
// ---------------------------------------------------------------------------

#define NELEM 16777216   // 4096*4096
#define KTOT  4096
#define BM 128
#define BN 128
#define BK 32
#define STAGES 4
#define ROWB 80          // 32 halves = 64B + 16B pad (conflict-free ldmatrix)
#define STAGE_BYTES ((BM + BN) * ROWB)   // 20480; x4 = 81920; x2 CTA = 160KB
#define NKT (KTOT / BK)  // 128

// Scratch (__device__ globals: allocation-free rule)
__device__ __align__(128) __half g_xh[(size_t)NELEM];   // x as fp16
__device__ __align__(128) __half g_qwh[(size_t)NELEM];  // ternary weight, fp16
__device__ float g_part[2048];
__device__ float g_scales[2];   // [0]=input_scale, [1]=w_scale

// ------------------------------ helpers -----------------------------------
__device__ __forceinline__ uint32_t smem_u32(const void* p) {
    uint32_t a;
    asm("{ .reg .u64 t; cvta.to.shared.u64 t, %1; cvt.u32.u64 %0, t; }"
        : "=r"(a) : "l"(p));
    return a;
}
__device__ __forceinline__ void cp16(uint32_t s, const void* g) {
    asm volatile("cp.async.cg.shared.global [%0], [%1], 16;" :: "r"(s), "l"(g));
}
__device__ __forceinline__ void ldmx4(uint32_t r[4], uint32_t addr) {
    asm volatile("ldmatrix.sync.aligned.m8n8.x4.shared.b16 {%0,%1,%2,%3}, [%4];"
                 : "=r"(r[0]), "=r"(r[1]), "=r"(r[2]), "=r"(r[3]) : "r"(addr));
}
__device__ __forceinline__ void mma16816(float c[4], const uint32_t a[4],
                                         uint32_t b0, uint32_t b1) {
    asm volatile(
        "mma.sync.aligned.m16n8k16.row.col.f32.f16.f16.f32 "
        "{%0,%1,%2,%3}, {%4,%5,%6,%7}, {%8,%9}, {%0,%1,%2,%3};"
        : "+f"(c[0]), "+f"(c[1]), "+f"(c[2]), "+f"(c[3])
        : "r"(a[0]), "r"(a[1]), "r"(a[2]), "r"(a[3]), "r"(b0), "r"(b1));
}

// ---------------------------------------------------------------------------
// Pass 1: abs-sum partials (fp32): x blocks 0..1023 (fused fp16 convert),
// w blocks 1024..2047.  Grid-stride loop unrolled x4 with front-batched
// loads: 16 iterations exactly -> 4 quads, no bounds checks. Additions in
// original element order -> bitwise-identical partials.
// ---------------------------------------------------------------------------
__global__ void k_reduce(const float* __restrict__ x, const float* __restrict__ w,
                         int n4) {
    const int isW = (blockIdx.x >= 1024);
    const float4* p = (const float4*)(isW ? w : x);
    __half2* q = (__half2*)g_xh;
    const int b0 = isW ? (blockIdx.x - 1024) : blockIdx.x;
    const int stride = 1024 * blockDim.x;           // 262144; n4/stride = 16
    float s0 = 0.f, s1 = 0.f, s2 = 0.f, s3 = 0.f;
    int i = b0 * blockDim.x + threadIdx.x;
#pragma unroll 1
    for (int it = 0; it < 4; it++) {                // 4 quads of 4 iterations
        float4 v0 = p[i];
        float4 v1 = p[i + stride];
        float4 v2 = p[i + 2 * stride];
        float4 v3 = p[i + 3 * stride];
        // same per-element order as the rolled loop:
        s0 += fabsf(v0.x); s1 += fabsf(v0.y); s2 += fabsf(v0.z); s3 += fabsf(v0.w);
        s0 += fabsf(v1.x); s1 += fabsf(v1.y); s2 += fabsf(v1.z); s3 += fabsf(v1.w);
        s0 += fabsf(v2.x); s1 += fabsf(v2.y); s2 += fabsf(v2.z); s3 += fabsf(v2.w);
        s0 += fabsf(v3.x); s1 += fabsf(v3.y); s2 += fabsf(v3.z); s3 += fabsf(v3.w);
        if (!isW) {
            q[2 * (size_t)i]                    = __floats2half2_rn(v0.x, v0.y);
            q[2 * (size_t)i + 1]                = __floats2half2_rn(v0.z, v0.w);
            q[2 * (size_t)(i + stride)]         = __floats2half2_rn(v1.x, v1.y);
            q[2 * (size_t)(i + stride) + 1]     = __floats2half2_rn(v1.z, v1.w);
            q[2 * (size_t)(i + 2 * stride)]     = __floats2half2_rn(v2.x, v2.y);
            q[2 * (size_t)(i + 2 * stride) + 1] = __floats2half2_rn(v2.z, v2.w);
            q[2 * (size_t)(i + 3 * stride)]     = __floats2half2_rn(v3.x, v3.y);
            q[2 * (size_t)(i + 3 * stride) + 1] = __floats2half2_rn(v3.z, v3.w);
        }
        i += 4 * stride;
    }
    __shared__ float smd[256];
    smd[threadIdx.x] = (s0 + s1) + (s2 + s3);
    __syncthreads();
    for (int o = 128; o > 0; o >>= 1) {
        if (threadIdx.x < o) smd[threadIdx.x] += smd[threadIdx.x + o];
        __syncthreads();
    }
    if (threadIdx.x == 0) g_part[blockIdx.x] = smd[0];
}

// ---------------------------------------------------------------------------
// Pass 2: quantize. Each block derives w_scale from the partials itself
// (bitwise identical across blocks). Block 0 publishes both scales.
// Main loop unrolled x2 (8 iterations exactly -> 4 pairs).
// ---------------------------------------------------------------------------
__global__ void k_quant(const float* __restrict__ w, int n4) {
    __shared__ float smd[256];
    const int tid = threadIdx.x;
    float sw = 0.f;
    for (int i = tid; i < 1024; i += 256) sw += g_part[1024 + i];
    smd[tid] = sw;
    __syncthreads();
    for (int o = 128; o > 0; o >>= 1) {
        if (tid < o) smd[tid] += smd[tid + o];
        __syncthreads();
    }
    const float s = fmaxf(smd[0] / (float)NELEM, 1e-8f);

    if (blockIdx.x == 0) {
        __syncthreads();
        float sx = 0.f;
        for (int i = tid; i < 1024; i += 256) sx += g_part[i];
        smd[tid] = sx;
        __syncthreads();
        for (int o = 128; o > 0; o >>= 1) {
            if (tid < o) smd[tid] += smd[tid + o];
            __syncthreads();
        }
        if (tid == 0) {
            g_scales[0] = fmaxf(smd[0] / (float)NELEM, 1e-8f);
            g_scales[1] = s;
        }
    }

    const __half one = __float2half(1.0f), mone = __float2half(-1.0f),
                 zero = __float2half(0.0f);
    const float4* p = (const float4*)w;
    __half2* q = (__half2*)g_qwh;
    const int stride = 2048 * 256;                  // 524288; n4/stride = 8
    int i = blockIdx.x * 256 + tid;
#pragma unroll 1
    for (int it = 0; it < 4; it++) {                // 4 pairs of 2 iterations
        float4 v0 = p[i];
        float4 v1 = p[i + stride];
        __half a0 = (fabsf(v0.x / s) > 0.5f) ? (v0.x > 0.f ? one : mone) : zero;
        __half a1 = (fabsf(v0.y / s) > 0.5f) ? (v0.y > 0.f ? one : mone) : zero;
        __half a2 = (fabsf(v0.z / s) > 0.5f) ? (v0.z > 0.f ? one : mone) : zero;
        __half a3 = (fabsf(v0.w / s) > 0.5f) ? (v0.w > 0.f ? one : mone) : zero;
        __half b0 = (fabsf(v1.x / s) > 0.5f) ? (v1.x > 0.f ? one : mone) : zero;
        __half b1 = (fabsf(v1.y / s) > 0.5f) ? (v1.y > 0.f ? one : mone) : zero;
        __half b2 = (fabsf(v1.z / s) > 0.5f) ? (v1.z > 0.f ? one : mone) : zero;
        __half b3 = (fabsf(v1.w / s) > 0.5f) ? (v1.w > 0.f ? one : mone) : zero;
        q[2 * (size_t)i]                = __halves2half2(a0, a1);
        q[2 * (size_t)i + 1]            = __halves2half2(a2, a3);
        q[2 * (size_t)(i + stride)]     = __halves2half2(b0, b1);
        q[2 * (size_t)(i + stride) + 1] = __halves2half2(b2, b3);
        i += 2 * stride;
    }
}

// ---------------------------------------------------------------------------
// Pass 3: GEMM — EXACT R9 kernel (frozen; 2D grid, BK=32, 4 stages,
// cross-barrier fragment pipelining, CTA 128x128 / warp 64x64, 2 CTAs/SM).
// ---------------------------------------------------------------------------
__global__ void __launch_bounds__(128, 2)
k_gemm(const float* __restrict__ bias, float* __restrict__ out) {
    extern __shared__ char smem[];
    const uint32_t sb = smem_u32(smem);

    const int tid  = threadIdx.x;
    const int warp = tid >> 5, lane = tid & 31;
    const int m0 = blockIdx.y * BM, n0 = blockIdx.x * BN;
    const int wm = (warp >> 1) * 64;   // 0 or 64
    const int wn = (warp & 1) * 64;    // 0 or 64
    const int grp = lane >> 2, tig = lane & 3;

    float acc[4][8][4];
#pragma unroll
    for (int i = 0; i < 4; i++)
#pragma unroll
        for (int j = 0; j < 8; j++)
#pragma unroll
            for (int r = 0; r < 4; r++) acc[i][j][r] = 0.f;

    const uint4* gA = (const uint4*)(g_xh  + (size_t)m0 * KTOT);
    const uint4* gB = (const uint4*)(g_qwh + (size_t)n0 * KTOT);

    const int lr = tid >> 2, lc = tid & 3;   // 4 sweeps of 32 rows

    auto issue = [&](int kt, int buf) {
        const uint32_t bA = sb + buf * STAGE_BYTES;
        const uint32_t bB = bA + BM * ROWB;
        const size_t gcol = (size_t)kt * 4 + lc;
#pragma unroll
        for (int i = 0; i < 4; i++) {
            const int r = lr + i * 32;
            cp16(bA + r * ROWB + lc * 16, gA + (size_t)r * 512 + gcol);
            cp16(bB + r * ROWB + lc * 16, gB + (size_t)r * 512 + gcol);
        }
    };

    const int lrow = lane & 15, lsel = lane >> 4;

    uint32_t a[2][4][4], b[2][4][4];

    auto loadFrag = [&](int buf, int ks, int pb) {
        const uint32_t bA = sb + buf * STAGE_BYTES;
        const uint32_t bB = bA + BM * ROWB;
        const uint32_t kcol = (uint32_t)(ks * 2 + lsel) * 16;
#pragma unroll
        for (int mi = 0; mi < 4; mi++)
            ldmx4(a[pb][mi], bA + (uint32_t)(wm + mi * 16 + lrow) * ROWB + kcol);
#pragma unroll
        for (int bi = 0; bi < 4; bi++)
            ldmx4(b[pb][bi], bB + (uint32_t)(wn + bi * 16 + lrow) * ROWB + kcol);
    };
    auto mmaStep = [&](int pb) {
#pragma unroll
        for (int mi = 0; mi < 4; mi++)
#pragma unroll
            for (int bi = 0; bi < 4; bi++) {
                mma16816(acc[mi][2 * bi],     a[pb][mi], b[pb][bi][0], b[pb][bi][2]);
                mma16816(acc[mi][2 * bi + 1], a[pb][mi], b[pb][bi][1], b[pb][bi][3]);
            }
    };

    issue(0, 0);
    asm volatile("cp.async.commit_group;" ::: "memory");
    issue(1, 1);
    asm volatile("cp.async.commit_group;" ::: "memory");
    issue(2, 2);
    asm volatile("cp.async.commit_group;" ::: "memory");
    asm volatile("cp.async.wait_group 2;" ::: "memory");
    __syncthreads();
    loadFrag(0, 0, 0);

    for (int kt = 0; kt < NKT; kt++) {
        const int cur = kt & 3;

        loadFrag(cur, 1, 1);               // ks1 frags (current stage)
        mmaStep(0);                        // HMMA ks0
        if (kt + 3 < NKT) issue(kt + 3, (kt + 3) & 3);
        asm volatile("cp.async.commit_group;" ::: "memory");
        asm volatile("cp.async.wait_group 2;" ::: "memory");
        __syncthreads();                   // stage kt+1 resident
        if (kt + 1 < NKT) loadFrag((kt + 1) & 3, 0, 0);  // next tile ks0
        mmaStep(1);                        //   hidden under ks1 HMMA block
    }

    const float ws = g_scales[1], is = g_scales[0];
#pragma unroll
    for (int mi = 0; mi < 4; mi++) {
        const int m = m0 + wm + mi * 16 + grp;
#pragma unroll
        for (int ni = 0; ni < 8; ni++) {
            const int n = n0 + wn + ni * 8 + tig * 2;
            const float2 bv = *(const float2*)&bias[n];
            float2 o0, o1;
            o0.x = acc[mi][ni][0] * ws + bv.x * is;
            o0.y = acc[mi][ni][1] * ws + bv.y * is;
            o1.x = acc[mi][ni][2] * ws + bv.x * is;
            o1.y = acc[mi][ni][3] * ws + bv.y * is;
            *(float2*)&out[(size_t)m * 4096 + n]       = o0;
            *(float2*)&out[(size_t)(m + 8) * 4096 + n] = o1;
        }
    }
}

// ---------------------------------------------------------------------------
extern "C" void kernel_launch(void* const* d_in, const int* in_sizes, int n_in,
                              void* d_out, int out_size) {
    const float* x    = (const float*)d_in[0];
    const float* w    = (const float*)d_in[1];
    const float* bias = (const float*)d_in[2];
    float* out = (float*)d_out;

    const int n4 = NELEM / 4;
    const int SMEM_BYTES = STAGES * STAGE_BYTES;  // 81920 (x2 CTAs = 160KB/SM)

    cudaFuncSetAttribute(k_gemm, cudaFuncAttributeMaxDynamicSharedMemorySize,
                         SMEM_BYTES);

    k_reduce<<<2048, 256>>>(x, w, n4);
    k_quant<<<2048, 256>>>(w, n4);

    dim3 grid(4096 / BN, 4096 / BM);  // (32, 32) — R9 exact
    k_gemm<<<grid, 128, SMEM_BYTES>>>(bias, out);
}

// round 16
// speedup vs baseline: 1.5088x; 1.5088x over previous
#include <cuda_runtime.h>
#include <cuda_fp16.h>
#include <cstdint>

// ---------------------------------------------------------------------------
// BitNetLinear (sm_103 portable path):
//   out = (x @ qw^T) * w_scale + bias * input_scale   (input_scale cancels in
//   the GEMM; x fed raw as fp16)
// GEMM M=N=K=4096: mma.sync.m16n8k16 fp16->fp32, ldmatrix.x4,
// CTA 128x128 / warp 64x64, BK=32, 4 stages, 2 CTAs/SM (R9, frozen).
// R16 = exact R9 with ONE change: k_reduce unrolled x4 (front-batched loads,
// MLP 1->4; measured 31->28us in isolation). k_quant reverted to R9 form.
// Controlled experiment to attribute R15's anomalous regression.
// ---------------------------------------------------------------------------

#define NELEM 16777216   // 4096*4096
#define KTOT  4096
#define BM 128
#define BN 128
#define BK 32
#define STAGES 4
#define ROWB 80          // 32 halves = 64B + 16B pad (conflict-free ldmatrix)
#define STAGE_BYTES ((BM + BN) * ROWB)   // 20480; x4 = 81920; x2 CTA = 160KB
#define NKT (KTOT / BK)  // 128

// Scratch (__device__ globals: allocation-free rule)
__device__ __align__(128) __half g_xh[(size_t)NELEM];   // x as fp16
__device__ __align__(128) __half g_qwh[(size_t)NELEM];  // ternary weight, fp16
__device__ float g_part[2048];
__device__ float g_scales[2];   // [0]=input_scale, [1]=w_scale

// ------------------------------ helpers -----------------------------------
__device__ __forceinline__ uint32_t smem_u32(const void* p) {
    uint32_t a;
    asm("{ .reg .u64 t; cvta.to.shared.u64 t, %1; cvt.u32.u64 %0, t; }"
        : "=r"(a) : "l"(p));
    return a;
}
__device__ __forceinline__ void cp16(uint32_t s, const void* g) {
    asm volatile("cp.async.cg.shared.global [%0], [%1], 16;" :: "r"(s), "l"(g));
}
__device__ __forceinline__ void ldmx4(uint32_t r[4], uint32_t addr) {
    asm volatile("ldmatrix.sync.aligned.m8n8.x4.shared.b16 {%0,%1,%2,%3}, [%4];"
                 : "=r"(r[0]), "=r"(r[1]), "=r"(r[2]), "=r"(r[3]) : "r"(addr));
}
__device__ __forceinline__ void mma16816(float c[4], const uint32_t a[4],
                                         uint32_t b0, uint32_t b1) {
    asm volatile(
        "mma.sync.aligned.m16n8k16.row.col.f32.f16.f16.f32 "
        "{%0,%1,%2,%3}, {%4,%5,%6,%7}, {%8,%9}, {%0,%1,%2,%3};"
        : "+f"(c[0]), "+f"(c[1]), "+f"(c[2]), "+f"(c[3])
        : "r"(a[0]), "r"(a[1]), "r"(a[2]), "r"(a[3]), "r"(b0), "r"(b1));
}

// ---------------------------------------------------------------------------
// Pass 1: abs-sum partials (fp32): x blocks 0..1023 (fused fp16 convert),
// w blocks 1024..2047.  Unrolled x4, front-batched loads (16 iters exact).
// Additions in original per-thread order -> bitwise-identical partials.
// ---------------------------------------------------------------------------
__global__ void k_reduce(const float* __restrict__ x, const float* __restrict__ w,
                         int n4) {
    const int isW = (blockIdx.x >= 1024);
    const float4* p = (const float4*)(isW ? w : x);
    __half2* q = (__half2*)g_xh;
    const int b0 = isW ? (blockIdx.x - 1024) : blockIdx.x;
    const int stride = 1024 * blockDim.x;           // 262144; n4/stride = 16
    float s0 = 0.f, s1 = 0.f, s2 = 0.f, s3 = 0.f;
    int i = b0 * blockDim.x + threadIdx.x;
#pragma unroll 1
    for (int it = 0; it < 4; it++) {                // 4 quads of 4 iterations
        float4 v0 = p[i];
        float4 v1 = p[i + stride];
        float4 v2 = p[i + 2 * stride];
        float4 v3 = p[i + 3 * stride];
        s0 += fabsf(v0.x); s1 += fabsf(v0.y); s2 += fabsf(v0.z); s3 += fabsf(v0.w);
        s0 += fabsf(v1.x); s1 += fabsf(v1.y); s2 += fabsf(v1.z); s3 += fabsf(v1.w);
        s0 += fabsf(v2.x); s1 += fabsf(v2.y); s2 += fabsf(v2.z); s3 += fabsf(v2.w);
        s0 += fabsf(v3.x); s1 += fabsf(v3.y); s2 += fabsf(v3.z); s3 += fabsf(v3.w);
        if (!isW) {
            q[2 * (size_t)i]                    = __floats2half2_rn(v0.x, v0.y);
            q[2 * (size_t)i + 1]                = __floats2half2_rn(v0.z, v0.w);
            q[2 * (size_t)(i + stride)]         = __floats2half2_rn(v1.x, v1.y);
            q[2 * (size_t)(i + stride) + 1]     = __floats2half2_rn(v1.z, v1.w);
            q[2 * (size_t)(i + 2 * stride)]     = __floats2half2_rn(v2.x, v2.y);
            q[2 * (size_t)(i + 2 * stride) + 1] = __floats2half2_rn(v2.z, v2.w);
            q[2 * (size_t)(i + 3 * stride)]     = __floats2half2_rn(v3.x, v3.y);
            q[2 * (size_t)(i + 3 * stride) + 1] = __floats2half2_rn(v3.z, v3.w);
        }
        i += 4 * stride;
    }
    __shared__ float smd[256];
    smd[threadIdx.x] = (s0 + s1) + (s2 + s3);
    __syncthreads();
    for (int o = 128; o > 0; o >>= 1) {
        if (threadIdx.x < o) smd[threadIdx.x] += smd[threadIdx.x + o];
        __syncthreads();
    }
    if (threadIdx.x == 0) g_part[blockIdx.x] = smd[0];
}

// ---------------------------------------------------------------------------
// Pass 2: quantize (EXACT R9 version). Each block derives w_scale from the
// partials itself (bitwise identical across blocks). Block 0 publishes scales.
// ---------------------------------------------------------------------------
__global__ void k_quant(const float* __restrict__ w, int n4) {
    __shared__ float smd[256];
    const int tid = threadIdx.x;
    float sw = 0.f;
    for (int i = tid; i < 1024; i += 256) sw += g_part[1024 + i];
    smd[tid] = sw;
    __syncthreads();
    for (int o = 128; o > 0; o >>= 1) {
        if (tid < o) smd[tid] += smd[tid + o];
        __syncthreads();
    }
    const float s = fmaxf(smd[0] / (float)NELEM, 1e-8f);

    if (blockIdx.x == 0) {
        __syncthreads();
        float sx = 0.f;
        for (int i = tid; i < 1024; i += 256) sx += g_part[i];
        smd[tid] = sx;
        __syncthreads();
        for (int o = 128; o > 0; o >>= 1) {
            if (tid < o) smd[tid] += smd[tid + o];
            __syncthreads();
        }
        if (tid == 0) {
            g_scales[0] = fmaxf(smd[0] / (float)NELEM, 1e-8f);
            g_scales[1] = s;
        }
    }

    const __half one = __float2half(1.0f), mone = __float2half(-1.0f),
                 zero = __float2half(0.0f);
    const float4* p = (const float4*)w;
    __half2* q = (__half2*)g_qwh;
    for (int i = blockIdx.x * blockDim.x + tid; i < n4;
         i += gridDim.x * blockDim.x) {
        float4 v = p[i];
        __half h0 = (fabsf(v.x / s) > 0.5f) ? (v.x > 0.f ? one : mone) : zero;
        __half h1 = (fabsf(v.y / s) > 0.5f) ? (v.y > 0.f ? one : mone) : zero;
        __half h2 = (fabsf(v.z / s) > 0.5f) ? (v.z > 0.f ? one : mone) : zero;
        __half h3 = (fabsf(v.w / s) > 0.5f) ? (v.w > 0.f ? one : mone) : zero;
        q[2 * i]     = __halves2half2(h0, h1);
        q[2 * i + 1] = __halves2half2(h2, h3);
    }
}

// ---------------------------------------------------------------------------
// Pass 3: GEMM — EXACT R9 kernel (frozen).
// ---------------------------------------------------------------------------
__global__ void __launch_bounds__(128, 2)
k_gemm(const float* __restrict__ bias, float* __restrict__ out) {
    extern __shared__ char smem[];
    const uint32_t sb = smem_u32(smem);

    const int tid  = threadIdx.x;
    const int warp = tid >> 5, lane = tid & 31;
    const int m0 = blockIdx.y * BM, n0 = blockIdx.x * BN;
    const int wm = (warp >> 1) * 64;   // 0 or 64
    const int wn = (warp & 1) * 64;    // 0 or 64
    const int grp = lane >> 2, tig = lane & 3;

    float acc[4][8][4];
#pragma unroll
    for (int i = 0; i < 4; i++)
#pragma unroll
        for (int j = 0; j < 8; j++)
#pragma unroll
            for (int r = 0; r < 4; r++) acc[i][j][r] = 0.f;

    const uint4* gA = (const uint4*)(g_xh  + (size_t)m0 * KTOT);
    const uint4* gB = (const uint4*)(g_qwh + (size_t)n0 * KTOT);

    const int lr = tid >> 2, lc = tid & 3;   // 4 sweeps of 32 rows

    auto issue = [&](int kt, int buf) {
        const uint32_t bA = sb + buf * STAGE_BYTES;
        const uint32_t bB = bA + BM * ROWB;
        const size_t gcol = (size_t)kt * 4 + lc;
#pragma unroll
        for (int i = 0; i < 4; i++) {
            const int r = lr + i * 32;
            cp16(bA + r * ROWB + lc * 16, gA + (size_t)r * 512 + gcol);
            cp16(bB + r * ROWB + lc * 16, gB + (size_t)r * 512 + gcol);
        }
    };

    const int lrow = lane & 15, lsel = lane >> 4;

    uint32_t a[2][4][4], b[2][4][4];

    auto loadFrag = [&](int buf, int ks, int pb) {
        const uint32_t bA = sb + buf * STAGE_BYTES;
        const uint32_t bB = bA + BM * ROWB;
        const uint32_t kcol = (uint32_t)(ks * 2 + lsel) * 16;
#pragma unroll
        for (int mi = 0; mi < 4; mi++)
            ldmx4(a[pb][mi], bA + (uint32_t)(wm + mi * 16 + lrow) * ROWB + kcol);
#pragma unroll
        for (int bi = 0; bi < 4; bi++)
            ldmx4(b[pb][bi], bB + (uint32_t)(wn + bi * 16 + lrow) * ROWB + kcol);
    };
    auto mmaStep = [&](int pb) {
#pragma unroll
        for (int mi = 0; mi < 4; mi++)
#pragma unroll
            for (int bi = 0; bi < 4; bi++) {
                mma16816(acc[mi][2 * bi],     a[pb][mi], b[pb][bi][0], b[pb][bi][2]);
                mma16816(acc[mi][2 * bi + 1], a[pb][mi], b[pb][bi][1], b[pb][bi][3]);
            }
    };

    issue(0, 0);
    asm volatile("cp.async.commit_group;" ::: "memory");
    issue(1, 1);
    asm volatile("cp.async.commit_group;" ::: "memory");
    issue(2, 2);
    asm volatile("cp.async.commit_group;" ::: "memory");
    asm volatile("cp.async.wait_group 2;" ::: "memory");
    __syncthreads();
    loadFrag(0, 0, 0);

    for (int kt = 0; kt < NKT; kt++) {
        const int cur = kt & 3;

        loadFrag(cur, 1, 1);               // ks1 frags (current stage)
        mmaStep(0);                        // HMMA ks0
        if (kt + 3 < NKT) issue(kt + 3, (kt + 3) & 3);
        asm volatile("cp.async.commit_group;" ::: "memory");
        asm volatile("cp.async.wait_group 2;" ::: "memory");
        __syncthreads();                   // stage kt+1 resident
        if (kt + 1 < NKT) loadFrag((kt + 1) & 3, 0, 0);  // next tile ks0
        mmaStep(1);                        //   hidden under ks1 HMMA block
    }

    const float ws = g_scales[1], is = g_scales[0];
#pragma unroll
    for (int mi = 0; mi < 4; mi++) {
        const int m = m0 + wm + mi * 16 + grp;
#pragma unroll
        for (int ni = 0; ni < 8; ni++) {
            const int n = n0 + wn + ni * 8 + tig * 2;
            const float2 bv = *(const float2*)&bias[n];
            float2 o0, o1;
            o0.x = acc[mi][ni][0] * ws + bv.x * is;
            o0.y = acc[mi][ni][1] * ws + bv.y * is;
            o1.x = acc[mi][ni][2] * ws + bv.x * is;
            o1.y = acc[mi][ni][3] * ws + bv.y * is;
            *(float2*)&out[(size_t)m * 4096 + n]       = o0;
            *(float2*)&out[(size_t)(m + 8) * 4096 + n] = o1;
        }
    }
}

// ---------------------------------------------------------------------------
extern "C" void kernel_launch(void* const* d_in, const int* in_sizes, int n_in,
                              void* d_out, int out_size) {
    const float* x    = (const float*)d_in[0];
    const float* w    = (const float*)d_in[1];
    const float* bias = (const float*)d_in[2];
    float* out = (float*)d_out;

    const int n4 = NELEM / 4;
    const int SMEM_BYTES = STAGES * STAGE_BYTES;  // 81920 (x2 CTAs = 160KB/SM)

    cudaFuncSetAttribute(k_gemm, cudaFuncAttributeMaxDynamicSharedMemorySize,
                         SMEM_BYTES);

    k_reduce<<<2048, 256>>>(x, w, n4);
    k_quant<<<2048, 256>>>(w, n4);

    dim3 grid(4096 / BN, 4096 / BM);  // (32, 32) — R9 exact
    k_gemm<<<grid, 128, SMEM_BYTES>>>(bias, out);
}

// round 17
// speedup vs baseline: 1.5098x; 1.0006x over previous
#include <cuda_runtime.h>
#include <cuda_fp16.h>
#include <cstdint>

// ---------------------------------------------------------------------------
// BitNetLinear (sm_103 portable path):
//   out = (x @ qw^T) * w_scale + bias * input_scale   (input_scale cancels in
//   the GEMM; x fed raw as fp16)
// GEMM M=N=K=4096: mma.sync.m16n8k16 fp16->fp32, ldmatrix.x4,
// CTA 128x128 / warp 64x64, BK=32, 4 stages, 2 CTAs/SM (R9, frozen).
// R17 = exact R16 with ONE change: k_quant main loop unrolled x2
// (front-batched loads, MLP 1->2; retry of R15's k_quant half in isolation).
// ---------------------------------------------------------------------------

#define NELEM 16777216   // 4096*4096
#define KTOT  4096
#define BM 128
#define BN 128
#define BK 32
#define STAGES 4
#define ROWB 80          // 32 halves = 64B + 16B pad (conflict-free ldmatrix)
#define STAGE_BYTES ((BM + BN) * ROWB)   // 20480; x4 = 81920; x2 CTA = 160KB
#define NKT (KTOT / BK)  // 128

// Scratch (__device__ globals: allocation-free rule)
__device__ __align__(128) __half g_xh[(size_t)NELEM];   // x as fp16
__device__ __align__(128) __half g_qwh[(size_t)NELEM];  // ternary weight, fp16
__device__ float g_part[2048];
__device__ float g_scales[2];   // [0]=input_scale, [1]=w_scale

// ------------------------------ helpers -----------------------------------
__device__ __forceinline__ uint32_t smem_u32(const void* p) {
    uint32_t a;
    asm("{ .reg .u64 t; cvta.to.shared.u64 t, %1; cvt.u32.u64 %0, t; }"
        : "=r"(a) : "l"(p));
    return a;
}
__device__ __forceinline__ void cp16(uint32_t s, const void* g) {
    asm volatile("cp.async.cg.shared.global [%0], [%1], 16;" :: "r"(s), "l"(g));
}
__device__ __forceinline__ void ldmx4(uint32_t r[4], uint32_t addr) {
    asm volatile("ldmatrix.sync.aligned.m8n8.x4.shared.b16 {%0,%1,%2,%3}, [%4];"
                 : "=r"(r[0]), "=r"(r[1]), "=r"(r[2]), "=r"(r[3]) : "r"(addr));
}
__device__ __forceinline__ void mma16816(float c[4], const uint32_t a[4],
                                         uint32_t b0, uint32_t b1) {
    asm volatile(
        "mma.sync.aligned.m16n8k16.row.col.f32.f16.f16.f32 "
        "{%0,%1,%2,%3}, {%4,%5,%6,%7}, {%8,%9}, {%0,%1,%2,%3};"
        : "+f"(c[0]), "+f"(c[1]), "+f"(c[2]), "+f"(c[3])
        : "r"(a[0]), "r"(a[1]), "r"(a[2]), "r"(a[3]), "r"(b0), "r"(b1));
}

// ---------------------------------------------------------------------------
// Pass 1: abs-sum partials (fp32): x blocks 0..1023 (fused fp16 convert),
// w blocks 1024..2047.  Unrolled x4, front-batched loads (verified R16).
// ---------------------------------------------------------------------------
__global__ void k_reduce(const float* __restrict__ x, const float* __restrict__ w,
                         int n4) {
    const int isW = (blockIdx.x >= 1024);
    const float4* p = (const float4*)(isW ? w : x);
    __half2* q = (__half2*)g_xh;
    const int b0 = isW ? (blockIdx.x - 1024) : blockIdx.x;
    const int stride = 1024 * blockDim.x;           // 262144; n4/stride = 16
    float s0 = 0.f, s1 = 0.f, s2 = 0.f, s3 = 0.f;
    int i = b0 * blockDim.x + threadIdx.x;
#pragma unroll 1
    for (int it = 0; it < 4; it++) {                // 4 quads of 4 iterations
        float4 v0 = p[i];
        float4 v1 = p[i + stride];
        float4 v2 = p[i + 2 * stride];
        float4 v3 = p[i + 3 * stride];
        s0 += fabsf(v0.x); s1 += fabsf(v0.y); s2 += fabsf(v0.z); s3 += fabsf(v0.w);
        s0 += fabsf(v1.x); s1 += fabsf(v1.y); s2 += fabsf(v1.z); s3 += fabsf(v1.w);
        s0 += fabsf(v2.x); s1 += fabsf(v2.y); s2 += fabsf(v2.z); s3 += fabsf(v2.w);
        s0 += fabsf(v3.x); s1 += fabsf(v3.y); s2 += fabsf(v3.z); s3 += fabsf(v3.w);
        if (!isW) {
            q[2 * (size_t)i]                    = __floats2half2_rn(v0.x, v0.y);
            q[2 * (size_t)i + 1]                = __floats2half2_rn(v0.z, v0.w);
            q[2 * (size_t)(i + stride)]         = __floats2half2_rn(v1.x, v1.y);
            q[2 * (size_t)(i + stride) + 1]     = __floats2half2_rn(v1.z, v1.w);
            q[2 * (size_t)(i + 2 * stride)]     = __floats2half2_rn(v2.x, v2.y);
            q[2 * (size_t)(i + 2 * stride) + 1] = __floats2half2_rn(v2.z, v2.w);
            q[2 * (size_t)(i + 3 * stride)]     = __floats2half2_rn(v3.x, v3.y);
            q[2 * (size_t)(i + 3 * stride) + 1] = __floats2half2_rn(v3.z, v3.w);
        }
        i += 4 * stride;
    }
    __shared__ float smd[256];
    smd[threadIdx.x] = (s0 + s1) + (s2 + s3);
    __syncthreads();
    for (int o = 128; o > 0; o >>= 1) {
        if (threadIdx.x < o) smd[threadIdx.x] += smd[threadIdx.x + o];
        __syncthreads();
    }
    if (threadIdx.x == 0) g_part[blockIdx.x] = smd[0];
}

// ---------------------------------------------------------------------------
// Pass 2: quantize. Each block derives w_scale from the partials itself
// (bitwise identical across blocks). Block 0 publishes both scales.
// Main loop unrolled x2, front-batched loads (8 iterations exact -> 4 pairs).
// ---------------------------------------------------------------------------
__global__ void k_quant(const float* __restrict__ w, int n4) {
    __shared__ float smd[256];
    const int tid = threadIdx.x;
    float sw = 0.f;
    for (int i = tid; i < 1024; i += 256) sw += g_part[1024 + i];
    smd[tid] = sw;
    __syncthreads();
    for (int o = 128; o > 0; o >>= 1) {
        if (tid < o) smd[tid] += smd[tid + o];
        __syncthreads();
    }
    const float s = fmaxf(smd[0] / (float)NELEM, 1e-8f);

    if (blockIdx.x == 0) {
        __syncthreads();
        float sx = 0.f;
        for (int i = tid; i < 1024; i += 256) sx += g_part[i];
        smd[tid] = sx;
        __syncthreads();
        for (int o = 128; o > 0; o >>= 1) {
            if (tid < o) smd[tid] += smd[tid + o];
            __syncthreads();
        }
        if (tid == 0) {
            g_scales[0] = fmaxf(smd[0] / (float)NELEM, 1e-8f);
            g_scales[1] = s;
        }
    }

    const __half one = __float2half(1.0f), mone = __float2half(-1.0f),
                 zero = __float2half(0.0f);
    const float4* p = (const float4*)w;
    __half2* q = (__half2*)g_qwh;
    const int stride = 2048 * 256;                  // 524288; n4/stride = 8
    int i = blockIdx.x * 256 + tid;
#pragma unroll 1
    for (int it = 0; it < 4; it++) {                // 4 pairs of 2 iterations
        float4 v0 = p[i];
        float4 v1 = p[i + stride];
        __half a0 = (fabsf(v0.x / s) > 0.5f) ? (v0.x > 0.f ? one : mone) : zero;
        __half a1 = (fabsf(v0.y / s) > 0.5f) ? (v0.y > 0.f ? one : mone) : zero;
        __half a2 = (fabsf(v0.z / s) > 0.5f) ? (v0.z > 0.f ? one : mone) : zero;
        __half a3 = (fabsf(v0.w / s) > 0.5f) ? (v0.w > 0.f ? one : mone) : zero;
        __half b0 = (fabsf(v1.x / s) > 0.5f) ? (v1.x > 0.f ? one : mone) : zero;
        __half b1 = (fabsf(v1.y / s) > 0.5f) ? (v1.y > 0.f ? one : mone) : zero;
        __half b2 = (fabsf(v1.z / s) > 0.5f) ? (v1.z > 0.f ? one : mone) : zero;
        __half b3 = (fabsf(v1.w / s) > 0.5f) ? (v1.w > 0.f ? one : mone) : zero;
        q[2 * (size_t)i]                = __halves2half2(a0, a1);
        q[2 * (size_t)i + 1]            = __halves2half2(a2, a3);
        q[2 * (size_t)(i + stride)]     = __halves2half2(b0, b1);
        q[2 * (size_t)(i + stride) + 1] = __halves2half2(b2, b3);
        i += 2 * stride;
    }
}

// ---------------------------------------------------------------------------
// Pass 3: GEMM — EXACT R9 kernel (frozen).
// ---------------------------------------------------------------------------
__global__ void __launch_bounds__(128, 2)
k_gemm(const float* __restrict__ bias, float* __restrict__ out) {
    extern __shared__ char smem[];
    const uint32_t sb = smem_u32(smem);

    const int tid  = threadIdx.x;
    const int warp = tid >> 5, lane = tid & 31;
    const int m0 = blockIdx.y * BM, n0 = blockIdx.x * BN;
    const int wm = (warp >> 1) * 64;   // 0 or 64
    const int wn = (warp & 1) * 64;    // 0 or 64
    const int grp = lane >> 2, tig = lane & 3;

    float acc[4][8][4];
#pragma unroll
    for (int i = 0; i < 4; i++)
#pragma unroll
        for (int j = 0; j < 8; j++)
#pragma unroll
            for (int r = 0; r < 4; r++) acc[i][j][r] = 0.f;

    const uint4* gA = (const uint4*)(g_xh  + (size_t)m0 * KTOT);
    const uint4* gB = (const uint4*)(g_qwh + (size_t)n0 * KTOT);

    const int lr = tid >> 2, lc = tid & 3;   // 4 sweeps of 32 rows

    auto issue = [&](int kt, int buf) {
        const uint32_t bA = sb + buf * STAGE_BYTES;
        const uint32_t bB = bA + BM * ROWB;
        const size_t gcol = (size_t)kt * 4 + lc;
#pragma unroll
        for (int i = 0; i < 4; i++) {
            const int r = lr + i * 32;
            cp16(bA + r * ROWB + lc * 16, gA + (size_t)r * 512 + gcol);
            cp16(bB + r * ROWB + lc * 16, gB + (size_t)r * 512 + gcol);
        }
    };

    const int lrow = lane & 15, lsel = lane >> 4;

    uint32_t a[2][4][4], b[2][4][4];

    auto loadFrag = [&](int buf, int ks, int pb) {
        const uint32_t bA = sb + buf * STAGE_BYTES;
        const uint32_t bB = bA + BM * ROWB;
        const uint32_t kcol = (uint32_t)(ks * 2 + lsel) * 16;
#pragma unroll
        for (int mi = 0; mi < 4; mi++)
            ldmx4(a[pb][mi], bA + (uint32_t)(wm + mi * 16 + lrow) * ROWB + kcol);
#pragma unroll
        for (int bi = 0; bi < 4; bi++)
            ldmx4(b[pb][bi], bB + (uint32_t)(wn + bi * 16 + lrow) * ROWB + kcol);
    };
    auto mmaStep = [&](int pb) {
#pragma unroll
        for (int mi = 0; mi < 4; mi++)
#pragma unroll
            for (int bi = 0; bi < 4; bi++) {
                mma16816(acc[mi][2 * bi],     a[pb][mi], b[pb][bi][0], b[pb][bi][2]);
                mma16816(acc[mi][2 * bi + 1], a[pb][mi], b[pb][bi][1], b[pb][bi][3]);
            }
    };

    issue(0, 0);
    asm volatile("cp.async.commit_group;" ::: "memory");
    issue(1, 1);
    asm volatile("cp.async.commit_group;" ::: "memory");
    issue(2, 2);
    asm volatile("cp.async.commit_group;" ::: "memory");
    asm volatile("cp.async.wait_group 2;" ::: "memory");
    __syncthreads();
    loadFrag(0, 0, 0);

    for (int kt = 0; kt < NKT; kt++) {
        const int cur = kt & 3;

        loadFrag(cur, 1, 1);               // ks1 frags (current stage)
        mmaStep(0);                        // HMMA ks0
        if (kt + 3 < NKT) issue(kt + 3, (kt + 3) & 3);
        asm volatile("cp.async.commit_group;" ::: "memory");
        asm volatile("cp.async.wait_group 2;" ::: "memory");
        __syncthreads();                   // stage kt+1 resident
        if (kt + 1 < NKT) loadFrag((kt + 1) & 3, 0, 0);  // next tile ks0
        mmaStep(1);                        //   hidden under ks1 HMMA block
    }

    const float ws = g_scales[1], is = g_scales[0];
#pragma unroll
    for (int mi = 0; mi < 4; mi++) {
        const int m = m0 + wm + mi * 16 + grp;
#pragma unroll
        for (int ni = 0; ni < 8; ni++) {
            const int n = n0 + wn + ni * 8 + tig * 2;
            const float2 bv = *(const float2*)&bias[n];
            float2 o0, o1;
            o0.x = acc[mi][ni][0] * ws + bv.x * is;
            o0.y = acc[mi][ni][1] * ws + bv.y * is;
            o1.x = acc[mi][ni][2] * ws + bv.x * is;
            o1.y = acc[mi][ni][3] * ws + bv.y * is;
            *(float2*)&out[(size_t)m * 4096 + n]       = o0;
            *(float2*)&out[(size_t)(m + 8) * 4096 + n] = o1;
        }
    }
}

// ---------------------------------------------------------------------------
extern "C" void kernel_launch(void* const* d_in, const int* in_sizes, int n_in,
                              void* d_out, int out_size) {
    const float* x    = (const float*)d_in[0];
    const float* w    = (const float*)d_in[1];
    const float* bias = (const float*)d_in[2];
    float* out = (float*)d_out;

    const int n4 = NELEM / 4;
    const int SMEM_BYTES = STAGES * STAGE_BYTES;  // 81920 (x2 CTAs = 160KB/SM)

    cudaFuncSetAttribute(k_gemm, cudaFuncAttributeMaxDynamicSharedMemorySize,
                         SMEM_BYTES);

    k_reduce<<<2048, 256>>>(x, w, n4);
    k_quant<<<2048, 256>>>(w, n4);

    dim3 grid(4096 / BN, 4096 / BM);  // (32, 32) — R9 exact
    k_gemm<<<grid, 128, SMEM_BYTES>>>(bias, out);
}